// round 16
// baseline (speedup 1.0000x reference)
#include <cuda_runtime.h>
#include <cuda_bf16.h>
#include <cuda_fp16.h>
#include <cstdint>
#include <math.h>

#define BB 4
#define LL 1024
#define DD 512
#define HH 8
#define HD 64
#define QKVD 1536
#define ML (BB*LL)
#define KH 512               // pure fp16 GEMM: K = 512
#define KTOP 716
#define THRESH 0.05f
#define SCALE 0.125f
#define NEG_INF __int_as_float(0xff800000)

#define NCHUNK (KH / 64)             // 8 chunks of K=64
#define STAGE_BYTES 32768            // A(16KB) + B(16KB) per stage
#define GM_DSM (3 * STAGE_BYTES + 128)

// Scratch (device globals; no allocations allowed)
__device__ float g_qkv[ML * QKVD];
__device__ float g_scores[(size_t)BB * HH * LL * LL];
__device__ float g_pw[BB * 3];
__device__ int   g_mode[BB];
__device__ float g_pool_part[128][DD];
// fp16 buffers
__device__ __half g_xh[ML * KH];
__device__ __half g_wqh[QKVD * KH];
__device__ __half g_ah[ML * KH];
__device__ __half g_pwh[DD * KH];

__device__ __forceinline__ uint32_t smem_u32(const void* p) {
    return (uint32_t)__cvta_generic_to_shared(p);
}
__device__ __forceinline__ void cp16(uint32_t dst, const void* src) {
    asm volatile("cp.async.cg.shared.global [%0], [%1], 16;\n" :: "r"(dst), "l"(src));
}
__device__ __forceinline__ uint32_t swz(uint32_t bufbase, int r, int u) {
    return bufbase + r * 128 + ((u ^ (r & 7)) << 4);
}

// ---------------------------------------------------------------------------
// fp32 -> fp16 convert, row-major [M][512].
// ---------------------------------------------------------------------------
__device__ __forceinline__ void cvt_row4(const float* src, __half* dst, int m, int c)
{
    float4 v = ((const float4*)(src + (size_t)m * DD))[c];
    __half2 h0 = {__float2half_rn(v.x), __float2half_rn(v.y)};
    __half2 h1 = {__float2half_rn(v.z), __float2half_rn(v.w)};
    __half2* d = (__half2*)(dst + (size_t)m * KH + c * 4);
    d[0] = h0; d[1] = h1;
}

__global__ __launch_bounds__(256)
void cvt_h(const float* __restrict__ src, __half* __restrict__ dst, int M)
{
    int i = blockIdx.x * 256 + threadIdx.x;
    int total = M * (DD / 4);
    if (i >= total) return;
    cvt_row4(src, dst, i / (DD / 4), i % (DD / 4));
}

// Both weight matrices in one launch.
__global__ __launch_bounds__(256)
void cvt_w(const float* __restrict__ wq, const float* __restrict__ wp,
           __half* __restrict__ dwq, __half* __restrict__ dwp)
{
    int i = blockIdx.x * 256 + threadIdx.x;
    int totq = QKVD * (DD / 4);
    int totp = DD * (DD / 4);
    if (i < totq) {
        cvt_row4(wq, dwq, i / (DD / 4), i % (DD / 4));
    } else if (i < totq + totp) {
        int j = i - totq;
        cvt_row4(wp, dwp, j / (DD / 4), j % (DD / 4));
    }
}

// ---------------------------------------------------------------------------
// fp16 NT GEMM via mma.sync m16n8k16, 3-stage cp.async pipeline,
// XOR-swizzled smem, one barrier per K-chunk. m_base allows row-split launches.
// ---------------------------------------------------------------------------
__global__ __launch_bounds__(256, 2)
void gemm_mma(const __half* __restrict__ A2,
              const __half* __restrict__ B2,
              float* __restrict__ C, int ldc, int N,
              const float* __restrict__ bias, int m_base)
{
    extern __shared__ char dsm[];
    uint32_t base = (smem_u32(dsm) + 127) & ~127u;
    int tid = threadIdx.x;
    int warp = tid >> 5, lane = tid & 31;
    int wm = warp >> 1, wn = warp & 1;
    int m0 = m_base + blockIdx.y * 128, n0 = blockIdx.x * 128;
    int m0w = wm * 32, n0w = wn * 64;

    float acc[2][8][4];
#pragma unroll
    for (int a = 0; a < 2; a++)
#pragma unroll
        for (int b = 0; b < 8; b++)
#pragma unroll
            for (int c = 0; c < 4; c++) acc[a][b][c] = 0.f;

    int u = tid & 7, row0 = tid >> 3;

    auto issue = [&](int chunk) {
        int s = chunk % 3;
        uint32_t bA = base + s * STAGE_BYTES;
        uint32_t bB = bA + 16384;
        int k0 = chunk * 64;
#pragma unroll
        for (int p = 0; p < 4; p++) {
            int r = row0 + p * 32;
            cp16(swz(bA, r, u), A2 + (size_t)(m0 + r) * KH + k0 + u * 8);
            cp16(swz(bB, r, u), B2 + (size_t)(n0 + r) * KH + k0 + u * 8);
        }
        asm volatile("cp.async.commit_group;\n");
    };

    issue(0);
    issue(1);

    for (int c = 0; c < NCHUNK; c++) {
        if (c + 2 < NCHUNK) {
            asm volatile("cp.async.wait_group 1;\n");
        } else {
            asm volatile("cp.async.wait_group 0;\n");
        }
        __syncthreads();
        if (c + 2 < NCHUNK) issue(c + 2);

        int s = c % 3;
        uint32_t bA = base + s * STAGE_BYTES;
        uint32_t bB = bA + 16384;
#pragma unroll
        for (int kk = 0; kk < 64; kk += 16) {
            int ub = kk >> 3;
            uint32_t a[2][4];
#pragma unroll
            for (int mt = 0; mt < 2; mt++) {
                int mrow = m0w + mt * 16 + (lane & 15);
                int un = ub + (lane >> 4);
                uint32_t ad = swz(bA, mrow, un);
                asm volatile("ldmatrix.sync.aligned.m8n8.x4.shared.b16 {%0,%1,%2,%3}, [%4];"
                    : "=r"(a[mt][0]), "=r"(a[mt][1]), "=r"(a[mt][2]), "=r"(a[mt][3])
                    : "r"(ad));
            }
            uint32_t bfr[4][4];
#pragma unroll
            for (int g = 0; g < 4; g++) {
                int nrow = n0w + g * 16 + ((lane >> 4) << 3) + (lane & 7);
                int un = ub + ((lane >> 3) & 1);
                uint32_t ad = swz(bB, nrow, un);
                asm volatile("ldmatrix.sync.aligned.m8n8.x4.shared.b16 {%0,%1,%2,%3}, [%4];"
                    : "=r"(bfr[g][0]), "=r"(bfr[g][1]), "=r"(bfr[g][2]), "=r"(bfr[g][3])
                    : "r"(ad));
            }
#pragma unroll
            for (int mt = 0; mt < 2; mt++)
#pragma unroll
                for (int nt = 0; nt < 8; nt++) {
                    int g = nt >> 1, pr = (nt & 1) * 2;
                    asm volatile(
                        "mma.sync.aligned.m16n8k16.row.col.f32.f16.f16.f32 "
                        "{%0,%1,%2,%3}, {%4,%5,%6,%7}, {%8,%9}, {%0,%1,%2,%3};"
                        : "+f"(acc[mt][nt][0]), "+f"(acc[mt][nt][1]),
                          "+f"(acc[mt][nt][2]), "+f"(acc[mt][nt][3])
                        : "r"(a[mt][0]), "r"(a[mt][1]), "r"(a[mt][2]), "r"(a[mt][3]),
                          "r"(bfr[g][pr]), "r"(bfr[g][pr + 1]));
                }
        }
    }

    // epilogue
#pragma unroll
    for (int mt = 0; mt < 2; mt++) {
        int mA = m0 + m0w + mt * 16 + (lane >> 2);
#pragma unroll
        for (int nt = 0; nt < 8; nt++) {
            int n = n0 + n0w + nt * 8 + (lane & 3) * 2;
            if (n >= N) continue;
            float b0 = bias ? bias[n] : 0.f;
            float b1 = bias ? bias[n + 1] : 0.f;
            *(float2*)&C[(size_t)mA * ldc + n] =
                make_float2(acc[mt][nt][0] + b0, acc[mt][nt][1] + b1);
            *(float2*)&C[(size_t)(mA + 8) * ldc + n] =
                make_float2(acc[mt][nt][2] + b0, acc[mt][nt][3] + b1);
        }
    }
}

// ---------------------------------------------------------------------------
// 128x128 fp32 SGEMM (NT) for the gated full-path scores.
// ---------------------------------------------------------------------------
__global__ __launch_bounds__(256)
void gemm128(const float* __restrict__ A, int lda, long sAb, long sAh,
             const float* __restrict__ B, int ldb, long sBb, long sBh,
             float* __restrict__ C, int ldc, long sCb, long sCh,
             int K, float alpha, const float* __restrict__ bias,
             int nh, const int* __restrict__ gate)
{
    __shared__ float As[16][132];
    __shared__ float Bs[16][132];
    int z = blockIdx.z;
    int b = z / nh, h = z % nh;
    if (gate && gate[b] != 0) return;
    A += (size_t)b * sAb + (size_t)h * sAh;
    B += (size_t)b * sBb + (size_t)h * sBh;
    C += (size_t)b * sCb + (size_t)h * sCh;

    int tid = threadIdx.x;
    int tx = tid & 15, ty = tid >> 4;
    int m0 = blockIdx.y * 128, n0 = blockIdx.x * 128;

    float acc[8][8];
#pragma unroll
    for (int i = 0; i < 8; i++)
#pragma unroll
        for (int j = 0; j < 8; j++) acc[i][j] = 0.f;

    for (int k0 = 0; k0 < K; k0 += 16) {
#pragma unroll
        for (int i = 0; i < 8; i++) {
            int idx = tid + i * 256;
            int m = idx >> 4, kk = idx & 15;
            As[kk][m] = A[(size_t)(m0 + m) * lda + k0 + kk];
            Bs[kk][m] = B[(size_t)(n0 + m) * ldb + k0 + kk];
        }
        __syncthreads();
#pragma unroll
        for (int kk = 0; kk < 16; kk++) {
            float4 a0 = *(const float4*)&As[kk][ty * 8];
            float4 a1 = *(const float4*)&As[kk][ty * 8 + 4];
            float4 b0 = *(const float4*)&Bs[kk][tx * 8];
            float4 b1 = *(const float4*)&Bs[kk][tx * 8 + 4];
            float av[8] = {a0.x, a0.y, a0.z, a0.w, a1.x, a1.y, a1.z, a1.w};
            float bv[8] = {b0.x, b0.y, b0.z, b0.w, b1.x, b1.y, b1.z, b1.w};
#pragma unroll
            for (int i = 0; i < 8; i++)
#pragma unroll
                for (int j = 0; j < 8; j++) acc[i][j] += av[i] * bv[j];
        }
        __syncthreads();
    }
#pragma unroll
    for (int i = 0; i < 8; i++) {
        int m = m0 + ty * 8 + i;
        float out[8];
#pragma unroll
        for (int j = 0; j < 8; j++) {
            out[j] = acc[i][j] * alpha;
            if (bias) out[j] += bias[n0 + tx * 8 + j];
        }
        float4* cp = (float4*)&C[(size_t)m * ldc + n0 + tx * 8];
        cp[0] = make_float4(out[0], out[1], out[2], out[3]);
        cp[1] = make_float4(out[4], out[5], out[6], out[7]);
    }
}

// ---------------------------------------------------------------------------
// 64x64 SGEMM (NN), AV path only: writes fp16 directly into g_ah.
// A = probs (z-strided), B = V rows in g_qkv. Row b*LL+m, col h*HD+n.
// ---------------------------------------------------------------------------
__global__ __launch_bounds__(256)
void gemm_av(const float* __restrict__ A, long sAz,
             const float* __restrict__ Bq,
             int K, const int* __restrict__ gate)
{
    __shared__ float As[16][65];
    __shared__ float Bs[16][65];
    int z = blockIdx.z;
    int b = z >> 3, h = z & 7;
    if (gate[b] != 0) return;
    A += (size_t)z * sAz;
    const float* B = Bq + (size_t)b * LL * QKVD + 2 * DD + h * HD;

    int tid = threadIdx.x;
    int tx = tid & 15, ty = tid >> 4;
    int m0 = blockIdx.y * 64, n0 = 0;

    float acc[4][4];
#pragma unroll
    for (int i = 0; i < 4; i++)
#pragma unroll
        for (int j = 0; j < 4; j++) acc[i][j] = 0.f;

    for (int k0 = 0; k0 < K; k0 += 16) {
#pragma unroll
        for (int i = 0; i < 4; i++) {
            int idx = tid + i * 256;
            int m = idx >> 4, kk = idx & 15;
            As[kk][m] = A[(size_t)(m0 + m) * LL + k0 + kk];
        }
#pragma unroll
        for (int i = 0; i < 4; i++) {
            int idx = tid + i * 256;
            int n = idx & 63, kk = idx >> 6;
            Bs[kk][n] = B[(size_t)(k0 + kk) * QKVD + n0 + n];
        }
        __syncthreads();
#pragma unroll
        for (int kk = 0; kk < 16; kk++) {
            float a[4], bb[4];
#pragma unroll
            for (int i = 0; i < 4; i++) a[i] = As[kk][ty * 4 + i];
#pragma unroll
            for (int j = 0; j < 4; j++) bb[j] = Bs[kk][tx * 4 + j];
#pragma unroll
            for (int i = 0; i < 4; i++)
#pragma unroll
                for (int j = 0; j < 4; j++) acc[i][j] += a[i] * bb[j];
        }
        __syncthreads();
    }
#pragma unroll
    for (int i = 0; i < 4; i++) {
        int m = b * LL + m0 + ty * 4 + i;
#pragma unroll
        for (int j = 0; j < 4; j++) {
            int col = h * HD + tx * 4 + j;
            g_ah[(size_t)m * KH + col] = __float2half_rn(acc[i][j]);
        }
    }
}

// ---------------------------------------------------------------------------
// Pooling stage 1: 128 blocks, each sums 32 rows of one batch.
// ---------------------------------------------------------------------------
__global__ __launch_bounds__(256)
void pool1_kernel(const float* __restrict__ x)
{
    int blk = blockIdx.x;
    int b = blk >> 5, c = blk & 31;
    int tid = threadIdx.x;
    const float2* xp = (const float2*)(x + ((size_t)b * LL + c * 32) * DD) + tid;
    float s0 = 0.f, s1 = 0.f;
    for (int l = 0; l < 32; l++) {
        float2 v = xp[(size_t)l * (DD / 2)];
        s0 += v.x; s1 += v.y;
    }
    g_pool_part[blk][tid * 2]     = s0;
    g_pool_part[blk][tid * 2 + 1] = s1;
}

// ---------------------------------------------------------------------------
__global__ __launch_bounds__(256)
void pattern_kernel(const float* __restrict__ w1, const float* __restrict__ b1,
                    const float* __restrict__ w2, const float* __restrict__ b2,
                    const float* __restrict__ w3, const float* __restrict__ b3,
                    const float* __restrict__ pbias)
{
    int b = blockIdx.x, tid = threadIdx.x;
    int warp = tid >> 5, lane = tid & 31;
    __shared__ float pooled[DD];
    __shared__ float h1[DD];
    __shared__ float h2[DD / 2];
    __shared__ float lg[3];

    for (int d = tid; d < DD; d += 256) {
        float s = 0.f;
#pragma unroll
        for (int c = 0; c < 32; c++) s += g_pool_part[b * 32 + c][d];
        pooled[d] = s * (1.0f / LL);
    }
    __syncthreads();
    for (int i = warp; i < DD; i += 8) {
        const float* wr = w1 + (size_t)i * DD;
        float a = 0.f;
        for (int k = lane; k < DD; k += 32) a += pooled[k] * wr[k];
#pragma unroll
        for (int o = 16; o > 0; o >>= 1) a += __shfl_xor_sync(~0u, a, o);
        if (lane == 0) h1[i] = fmaxf(a + b1[i], 0.f);
    }
    __syncthreads();
    for (int i = warp; i < DD / 2; i += 8) {
        const float* wr = w2 + (size_t)i * DD;
        float a = 0.f;
        for (int k = lane; k < DD; k += 32) a += h1[k] * wr[k];
#pragma unroll
        for (int o = 16; o > 0; o >>= 1) a += __shfl_xor_sync(~0u, a, o);
        if (lane == 0) h2[i] = fmaxf(a + b2[i], 0.f);
    }
    __syncthreads();
    if (warp < 3) {
        const float* wr = w3 + (size_t)warp * (DD / 2);
        float a = 0.f;
        for (int k = lane; k < DD / 2; k += 32) a += h2[k] * wr[k];
#pragma unroll
        for (int o = 16; o > 0; o >>= 1) a += __shfl_xor_sync(~0u, a, o);
        if (lane == 0) lg[warp] = (a + b3[warp] + pbias[warp]) / 0.3f;
    }
    __syncthreads();
    if (tid == 0) {
        float m = fmaxf(lg[0], fmaxf(lg[1], lg[2]));
        float e0 = expf(lg[0] - m), e1 = expf(lg[1] - m), e2 = expf(lg[2] - m);
        float inv = 1.f / (e0 + e1 + e2);
        float p0 = e0 * inv, p1 = e1 * inv, p2 = e2 * inv;
        g_pw[b * 3 + 0] = p0;
        g_pw[b * 3 + 1] = p1;
        g_pw[b * 3 + 2] = p2;
        bool A00 = p1 > THRESH;
        bool A01 = (p1 + p2) > THRESH;
        bool A10 = (p0 + p1) > THRESH;
        bool A11 = ((p0 + p1) + p2) > THRESH;
        bool need_sparse = (A00 != A01) || (A10 != A11);
        int mode;
        if (need_sparse || A00) mode = 0;
        else if (A10)           mode = 1;
        else                    mode = 2;
        g_mode[b] = mode;
    }
}

// ---------------------------------------------------------------------------
__device__ __forceinline__ void write_h(int m, int col, float v)
{
    g_ah[(size_t)m * KH + col] = __float2half_rn(v);
}

// ---------------------------------------------------------------------------
// Local-window fused attention (mode 1) + all-masked fallback (mode 2).
// ---------------------------------------------------------------------------
__global__ __launch_bounds__(256)
void local_attn_kernel(int b_off)
{
    __shared__ float ksh[48][65];
    __shared__ float vsh[48][65];
    __shared__ float qsh[16][64];
    __shared__ float psh[16][33];

    int blk = blockIdx.x;
    int b = b_off + (blk >> 9);
    int h = (blk >> 6) & 7;
    int q0 = (blk & 63) * 16;
    int mode = g_mode[b];
    if (mode == 0) return;
    int tid = threadIdx.x;
    const float* base = g_qkv + (size_t)b * LL * QKVD + h * HD;

    if (mode == 2) {
        const float* v0 = base + 2 * DD;
#pragma unroll
        for (int i = 0; i < 4; i++) {
            int idx = tid + i * 256;
            int r = idx >> 6, d = idx & 63;
            write_h(b * LL + q0 + r, h * HD + d, v0[d]);
        }
        return;
    }

    int kb0 = max(q0 - 16, 0);
    int kend = min(q0 + 15 + 16, LL - 1);
    int klen = kend - kb0 + 1;

    for (int i = tid; i < klen * 64; i += 256) {
        int jj = i >> 6, d = i & 63;
        const float* src = base + (size_t)(kb0 + jj) * QKVD;
        ksh[jj][d] = src[DD + d];
        vsh[jj][d] = src[2 * DD + d];
    }
#pragma unroll
    for (int i = 0; i < 4; i++) {
        int idx = tid + i * 256;
        int r = idx >> 6, d = idx & 63;
        qsh[r][d] = base[(size_t)(q0 + r) * QKVD + d];
    }
    __syncthreads();

    int warp = tid >> 5, lane = tid & 31;
#pragma unroll
    for (int rr = 0; rr < 2; rr++) {
        int r = warp * 2 + rr;
        int q = q0 + r;
        int w0 = max(q - 16, 0), w1 = min(q + 16, LL - 1);
        int cnt = w1 - w0 + 1;
        int off = w0 - kb0;

        float s0 = NEG_INF, s1 = NEG_INF;
        if (lane < cnt) {
            float acc = 0.f;
#pragma unroll
            for (int d = 0; d < 64; d++) acc += qsh[r][d] * ksh[off + lane][d];
            s0 = acc * SCALE;
        }
        if (lane + 32 < cnt) {
            float acc = 0.f;
#pragma unroll
            for (int d = 0; d < 64; d++) acc += qsh[r][d] * ksh[off + lane + 32][d];
            s1 = acc * SCALE;
        }
        float m = fmaxf(s0, s1);
#pragma unroll
        for (int o = 16; o > 0; o >>= 1) m = fmaxf(m, __shfl_xor_sync(~0u, m, o));
        float e0 = (lane < cnt) ? __expf(s0 - m) : 0.f;
        float e1 = (lane + 32 < cnt) ? __expf(s1 - m) : 0.f;
        float sum = e0 + e1;
#pragma unroll
        for (int o = 16; o > 0; o >>= 1) sum += __shfl_xor_sync(~0u, sum, o);
        float inv = 1.f / sum;
        if (lane < cnt) psh[r][lane] = e0 * inv;
        if (lane + 32 < cnt) psh[r][lane + 32] = e1 * inv;
        __syncwarp();

        float o0 = 0.f, o1 = 0.f;
        for (int jj = 0; jj < cnt; jj++) {
            float p = psh[r][jj];
            o0 += p * vsh[off + jj][lane];
            o1 += p * vsh[off + jj][lane + 32];
        }
        int m_out = b * LL + q;
        write_h(m_out, h * HD + lane, o0);
        write_h(m_out, h * HD + lane + 32, o1);
    }
}

// ---------------------------------------------------------------------------
// Full-path mask + softmax (mode 0 only). 64 rows per block.
// ---------------------------------------------------------------------------
__device__ __forceinline__ unsigned fkey(float f) {
    unsigned u = __float_as_uint(f);
    return (u & 0x80000000u) ? ~u : (u | 0x80000000u);
}

__global__ __launch_bounds__(256)
void softmax_kernel(const float* __restrict__ sparse_w,
                    const float* __restrict__ sparse_b)
{
    __shared__ float s[LL];
    __shared__ float red[256];
    __shared__ unsigned hist[256];
    __shared__ unsigned sel_prefix, sel_k;
    __shared__ float mx_sh;

    int grp = blockIdx.x;
    int z = grp >> 4;
    int b = z >> 3, h = z & 7;
    if (g_mode[b] != 0) return;
    int q_base = (grp & 15) * 64;
    int tid = threadIdx.x;

    float p0 = g_pw[b * 3 + 0];
    float p1 = g_pw[b * 3 + 1];
    float p2 = g_pw[b * 3 + 2];
    bool A00 = p1 > THRESH;
    bool A01 = (p1 + p2) > THRESH;
    bool A10 = (p0 + p1) > THRESH;
    bool A11 = ((p0 + p1) + p2) > THRESH;
    bool need_sparse = (A00 != A01) || (A10 != A11);
    float w_h = sparse_w[h], b_h = sparse_b[h];

    for (int r = 0; r < 64; r++) {
        int q = q_base + r;
        float* srow = g_scores + ((size_t)z << 20) + ((size_t)q << 10);
        ((float4*)s)[tid] = ((const float4*)srow)[tid];
        __syncthreads();

        unsigned tu = 0u;
        if (need_sparse) {
            if (tid == 0) { sel_prefix = 0u; sel_k = KTOP; }
            __syncthreads();
            for (int shift = 24; shift >= 0; shift -= 8) {
                hist[tid] = 0u;
                __syncthreads();
                unsigned pref = sel_prefix;
                unsigned hm = (shift == 24) ? 0u : (0xFFFFFFFFu << (shift + 8));
                for (int j = tid; j < LL; j += 256) {
                    float v = __fadd_rn(__fmul_rn(s[j], w_h), b_h);
                    unsigned u = fkey(v);
                    if ((u & hm) == pref) atomicAdd(&hist[(u >> shift) & 255u], 1u);
                }
                __syncthreads();
                if (tid == 0) {
                    unsigned k = sel_k, cum = 0;
                    for (int dgt = 255; dgt >= 0; --dgt) {
                        unsigned c = hist[dgt];
                        if (cum + c >= k) {
                            sel_prefix = pref | ((unsigned)dgt << shift);
                            sel_k = k - cum;
                            break;
                        }
                        cum += c;
                    }
                }
                __syncthreads();
            }
            tu = sel_prefix;
            __syncthreads();
        }

        float v[4];
        float lm = NEG_INF;
#pragma unroll
        for (int i = 0; i < 4; i++) {
            int j = tid * 4 + i;
            float sv = s[j];
            bool lf = (abs(q - j) <= 16);
            bool allow;
            if (need_sparse) {
                float s2 = __fadd_rn(__fmul_rn(sv, w_h), b_h);
                float sf = (fkey(s2) >= tu) ? 1.f : 0.f;
                float comb = (p0 * (lf ? 1.f : 0.f) + p1) + p2 * sf;
                allow = comb > THRESH;
            } else {
                allow = lf ? A10 : A00;
            }
            v[i] = allow ? sv : NEG_INF;
            lm = fmaxf(lm, v[i]);
        }
        red[tid] = lm; __syncthreads();
        for (int o = 128; o > 0; o >>= 1) {
            if (tid < o) red[tid] = fmaxf(red[tid], red[tid + o]);
            __syncthreads();
        }
        if (tid == 0) mx_sh = red[0];
        __syncthreads();
        float mx = mx_sh;

        if (mx == NEG_INF) {
            float4 o;
            o.x = (tid == 0) ? 1.f : 0.f; o.y = 0.f; o.z = 0.f; o.w = 0.f;
            ((float4*)srow)[tid] = o;
            __syncthreads();
            continue;
        }

        float ls = 0.f;
#pragma unroll
        for (int i = 0; i < 4; i++) {
            v[i] = __expf(v[i] - mx);
            ls += v[i];
        }
        red[tid] = ls; __syncthreads();
        for (int o = 128; o > 0; o >>= 1) {
            if (tid < o) red[tid] += red[tid + o];
            __syncthreads();
        }
        if (tid == 0) mx_sh = 1.f / red[0];
        __syncthreads();
        float inv = mx_sh;
        float4 o;
        o.x = v[0] * inv; o.y = v[1] * inv; o.z = v[2] * inv; o.w = v[3] * inv;
        ((float4*)srow)[tid] = o;
        __syncthreads();
    }
}

// ---------------------------------------------------------------------------
extern "C" void kernel_launch(void* const* d_in, const int* in_sizes, int n_in,
                              void* d_out, int out_size)
{
    const float* x        = (const float*)d_in[0];
    const float* qkv_w    = (const float*)d_in[1];
    const float* proj_w   = (const float*)d_in[2];
    const float* proj_b   = (const float*)d_in[3];
    const float* ps_w1    = (const float*)d_in[4];
    const float* ps_b1    = (const float*)d_in[5];
    const float* ps_w2    = (const float*)d_in[6];
    const float* ps_b2    = (const float*)d_in[7];
    const float* ps_w3    = (const float*)d_in[8];
    const float* ps_b3    = (const float*)d_in[9];
    const float* pbias    = (const float*)d_in[10];
    const float* sparse_w = (const float*)d_in[11];
    const float* sparse_b = (const float*)d_in[12];
    float* out = (float*)d_out;

    float *qkv_p, *sc_p;
    int *mode_p;
    __half *xh_p, *wqh_p, *ah_p, *pwh_p;
    cudaGetSymbolAddress((void**)&qkv_p,  g_qkv);
    cudaGetSymbolAddress((void**)&sc_p,   g_scores);
    cudaGetSymbolAddress((void**)&mode_p, g_mode);
    cudaGetSymbolAddress((void**)&xh_p,   g_xh);
    cudaGetSymbolAddress((void**)&wqh_p,  g_wqh);
    cudaGetSymbolAddress((void**)&ah_p,   g_ah);
    cudaGetSymbolAddress((void**)&pwh_p,  g_pwh);

    // One-time setup (first call is the uncaptured correctness run)
    static cudaStream_t s1 = nullptr, s2 = nullptr;
    static cudaEvent_t eFork = nullptr, eMode = nullptr, eW = nullptr,
                       eG1 = nullptr, eQkv = nullptr, eFull = nullptr,
                       eL123 = nullptr, eP02 = nullptr;
    if (!s1) {
        cudaStreamCreateWithFlags(&s1, cudaStreamNonBlocking);
        cudaStreamCreateWithFlags(&s2, cudaStreamNonBlocking);
        cudaEventCreateWithFlags(&eFork, cudaEventDisableTiming);
        cudaEventCreateWithFlags(&eMode, cudaEventDisableTiming);
        cudaEventCreateWithFlags(&eW,    cudaEventDisableTiming);
        cudaEventCreateWithFlags(&eG1,   cudaEventDisableTiming);
        cudaEventCreateWithFlags(&eQkv,  cudaEventDisableTiming);
        cudaEventCreateWithFlags(&eFull, cudaEventDisableTiming);
        cudaEventCreateWithFlags(&eL123, cudaEventDisableTiming);
        cudaEventCreateWithFlags(&eP02,  cudaEventDisableTiming);
        cudaFuncSetAttribute(gemm_mma, cudaFuncAttributeMaxDynamicSharedMemorySize, GM_DSM);
    }

    // Fork side streams off the main (capture-origin) stream
    cudaEventRecord(eFork, 0);
    cudaStreamWaitEvent(s1, eFork, 0);
    cudaStreamWaitEvent(s2, eFork, 0);

    // s1: pattern-selector chain -> g_mode
    pool1_kernel<<<128, 256, 0, s1>>>(x);
    pattern_kernel<<<BB, 256, 0, s1>>>(ps_w1, ps_b1, ps_w2, ps_b2, ps_w3, ps_b3, pbias);
    cudaEventRecord(eMode, s1);

    // s2: both weight conversions in one launch
    cvt_w<<<((QKVD + DD) * (DD / 4) + 255) / 256, 256, 0, s2>>>(
        qkv_w, proj_w, wqh_p, pwh_p);
    cudaEventRecord(eW, s2);

    // main: x conversion, then QKV GEMM split:
    // G1 = batches 0-2 (288 CTAs ~ one wave), G2 = batch 3 (96 CTAs).
    cvt_h<<<(ML * DD / 4 + 255) / 256, 256>>>(x, xh_p, ML);
    cudaStreamWaitEvent(0, eW, 0);
    gemm_mma<<<dim3(QKVD / 128, 24), 256, GM_DSM>>>(
        xh_p, wqh_p, qkv_p, QKVD, QKVD, nullptr, 0);
    cudaEventRecord(eG1, 0);
    gemm_mma<<<dim3(QKVD / 128, 8), 256, GM_DSM>>>(
        xh_p, wqh_p, qkv_p, QKVD, QKVD, nullptr, 3072);
    cudaEventRecord(eQkv, 0);

    // s2: local attention for batches 0-2 (needs G1 + mode), overlaps G2
    cudaStreamWaitEvent(s2, eG1, 0);
    cudaStreamWaitEvent(s2, eMode, 0);
    local_attn_kernel<<<3 * HH * (LL / 16), 256, 0, s2>>>(0);
    cudaEventRecord(eL123, s2);

    // s1: gated full path (needs full QKV; stubs when no batch is mode 0).
    // gemm_av writes fp16 directly into g_ah -> no separate cvt stage.
    cudaStreamWaitEvent(s1, eQkv, 0);
    gemm128<<<dim3(LL / 128, LL / 128, BB * HH), 256, 0, s1>>>(
        qkv_p, QKVD, (long)LL * QKVD, HD,
        qkv_p + DD, QKVD, (long)LL * QKVD, HD,
        sc_p, LL, (long)HH * LL * LL, (long)LL * LL,
        HD, SCALE, nullptr, HH, mode_p);
    softmax_kernel<<<BB * HH * (LL / 64), 256, 0, s1>>>(sparse_w, sparse_b);
    gemm_av<<<dim3(1, LL / 64, BB * HH), 256, 0, s1>>>(
        sc_p, (long)LL * LL, qkv_p, LL, mode_p);
    cudaEventRecord(eFull, s1);

    // s2: proj for batches 0-2 (needs L123 [program order] + gated AV + weights)
    cudaStreamWaitEvent(s2, eFull, 0);
    gemm_mma<<<dim3(DD / 128, 24), 256, GM_DSM, s2>>>(
        ah_p, pwh_p, out, DD, DD, proj_b, 0);
    cudaEventRecord(eP02, s2);

    // main: local attention for batch 3 (needs G2 [program order] + mode)
    cudaStreamWaitEvent(0, eMode, 0);
    local_attn_kernel<<<1 * HH * (LL / 16), 256>>>(3);

    // main: proj for batch 3 (needs L4 [program order] + gated AV + weights)
    cudaStreamWaitEvent(0, eFull, 0);
    gemm_mma<<<dim3(DD / 128, 8), 256, GM_DSM>>>(
        ah_p, pwh_p, out, DD, DD, proj_b, 3072);

    // join s2 (proj 0-2) back into the capture-origin stream
    cudaStreamWaitEvent(0, eP02, 0);
}